// round 6
// baseline (speedup 1.0000x reference)
#include <cuda_runtime.h>

// TopicNounAttention — warp-per-sample, un-normalized softmax (scores O(1) by
// construction). R6 = R5 theory with compilable PTX: L2 residency via
// createpolicy + ld.global.nc.L2::cache_hint.v4.f32 (the bare evict_last
// qualifier form requires 32B loads on this ptxas; rows are only 16B aligned).
//   we reads:  evict_last policy (pin 60MB table in 126MB L2 across replays)
//   out writes: st.global.cs (streaming, don't churn the pinned table)

#define VOCAB   50000
#define D_WORD  300
#define D_TOPIC 128
#define DH      312
#define LMAX    32

__device__ __align__(16) float g_ws[320];  // scaled projection vector, zero-padded

__global__ void prep_kernel(const float* __restrict__ topic_emb,
                            const float* __restrict__ k_w,
                            const float* __restrict__ q_w,
                            const float* __restrict__ q_b)
{
    __shared__ float te[D_TOPIC];
    __shared__ float q[D_TOPIC];
    const int t = threadIdx.x;
    if (t < D_TOPIC) te[t] = topic_emb[t];
    __syncthreads();
    if (t < D_TOPIC) {
        const float* row = q_w + t * D_TOPIC;
        float p0 = 0.f, p1 = 0.f, p2 = 0.f, p3 = 0.f;
        #pragma unroll
        for (int j = 0; j < D_TOPIC; j += 4) {
            p0 += row[j]     * te[j];
            p1 += row[j + 1] * te[j + 1];
            p2 += row[j + 2] * te[j + 2];
            p3 += row[j + 3] * te[j + 3];
        }
        q[t] = q_b[t] + (p0 + p1) + (p2 + p3);
    }
    __syncthreads();
    const float scale = 0.0883883476483184406f;  // 1/sqrt(128)
    if (t < 320) {
        float acc = 0.f;
        if (t < DH) {
            float p0 = 0.f, p1 = 0.f, p2 = 0.f, p3 = 0.f;
            #pragma unroll
            for (int i = 0; i < D_TOPIC; i += 4) {
                p0 += k_w[(i)     * DH + t] * q[i];
                p1 += k_w[(i + 1) * DH + t] * q[i + 1];
                p2 += k_w[(i + 2) * DH + t] * q[i + 2];
                p3 += k_w[(i + 3) * DH + t] * q[i + 3];
            }
            acc = ((p0 + p1) + (p2 + p3)) * scale;
        }
        g_ws[t] = acc;  // pads [312,320) with zero
    }
}

__device__ __forceinline__ float dot4(float4 a, float4 b) {
    return a.x * b.x + a.y * b.y + a.z * b.z + a.w * b.w;
}

// read-only 128-bit load with evict_last L2 policy (policy-register form,
// which unlike the inline qualifier supports .v4.f32)
__device__ __forceinline__ float4 ldg_keep(const float4* p, unsigned long long pol) {
    float4 v;
    asm volatile("ld.global.nc.L2::cache_hint.v4.f32 {%0,%1,%2,%3}, [%4], %5;"
                 : "=f"(v.x), "=f"(v.y), "=f"(v.z), "=f"(v.w)
                 : "l"(p), "l"(pol));
    return v;
}

// streaming store (evict-first): keep output traffic from churning the table
__device__ __forceinline__ void stg_cs(float4* p, float4 v) {
    asm volatile("st.global.cs.v4.f32 [%0], {%1,%2,%3,%4};"
                 :: "l"(p), "f"(v.x), "f"(v.y), "f"(v.z), "f"(v.w) : "memory");
}

__global__ void __launch_bounds__(128) attn_kernel(
    const int*   __restrict__ noun_ids,   // [B, 32]
    const int*   __restrict__ lengths,    // [B]
    const int*   __restrict__ months,     // [B]
    const void*  __restrict__ mie_ptr,    // scalar month_info_encode
    const float* __restrict__ we,         // [VOCAB, 300]
    float*       __restrict__ out,        // [B, 312]
    int B)
{
    const int lane = threadIdx.x & 31;
    const int b = blockIdx.x * 4 + (threadIdx.x >> 5);
    if (b >= B) return;

    unsigned long long pol;
    asm volatile("createpolicy.fractional.L2::evict_last.b64 %0, 1.0;" : "=l"(pol));

    float4* ob = reinterpret_cast<float4*>(out + (long long)b * DH);  // 1248B rows
    const int len0 = lengths[b];

    if (len0 <= 0) {
        const float4 z = make_float4(0.f, 0.f, 0.f, 0.f);
        stg_cs(ob + lane, z); stg_cs(ob + lane + 32, z);
        if (lane < 14) stg_cs(ob + lane + 64, z);
        return;
    }
    const int len   = (len0 < LMAX) ? len0 : LMAX;
    const int month = months[b];
    const unsigned mu = *(const unsigned*)mie_ptr;
    const float mie = (mu < 0x10000u) ? (float)(int)mu : __uint_as_float(mu);

    // projection vector slice in registers (w2 zero-padded for lanes >= 11)
    const float4* wsv = reinterpret_cast<const float4*>(g_ws);
    const float4 w0 = wsv[lane];
    const float4 w1 = wsv[lane + 32];
    float4 w2 = make_float4(0.f, 0.f, 0.f, 0.f);
    const bool tail = (lane < 11);
    if (tail) w2 = wsv[lane + 64];

    const int ids = noun_ids[b * LMAX + lane];

    float4 a0 = make_float4(0.f, 0.f, 0.f, 0.f), a1 = a0, a2 = a0;
    float denom = 0.f;

    #pragma unroll 2
    for (int l = 0; l < len; ++l) {
        const float4* r = reinterpret_cast<const float4*>(
            we + (long long)__shfl_sync(0xffffffffu, ids, l) * D_WORD);
        const float4 e0 = ldg_keep(r + lane, pol);
        const float4 e1 = ldg_keep(r + lane + 32, pol);
        float4 e2 = make_float4(0.f, 0.f, 0.f, 0.f);
        if (tail) e2 = ldg_keep(r + lane + 64, pol);   // predicated: avoids OOB

        float s = dot4(e0, w0) + dot4(e1, w1) + dot4(e2, w2);
        #pragma unroll
        for (int o = 16; o > 0; o >>= 1) s += __shfl_xor_sync(0xffffffffu, s, o);

        const float p = __expf(s);     // scores O(1): no max subtraction needed
        denom += p;
        a0.x += p * e0.x;  a0.y += p * e0.y;  a0.z += p * e0.z;  a0.w += p * e0.w;
        a1.x += p * e1.x;  a1.y += p * e1.y;  a1.z += p * e1.z;  a1.w += p * e1.w;
        a2.x += p * e2.x;  a2.y += p * e2.y;  a2.z += p * e2.z;  a2.w += p * e2.w;
    }

    const float inv = 1.f / denom;
    float4 o;
    o.x = a0.x * inv; o.y = a0.y * inv; o.z = a0.z * inv; o.w = a0.w * inv;
    stg_cs(ob + lane, o);
    o.x = a1.x * inv; o.y = a1.y * inv; o.z = a1.z * inv; o.w = a1.w * inv;
    stg_cs(ob + lane + 32, o);
    if (tail) {
        o.x = a2.x * inv; o.y = a2.y * inv; o.z = a2.z * inv; o.w = a2.w * inv;
        stg_cs(ob + lane + 64, o);
    } else if (lane < 14) {
        const int j0 = 4 * lane + 256 - 300;   // month one-hot block d in [300,312)
        o.x = (j0 + 0 == month) ? mie : 0.f;
        o.y = (j0 + 1 == month) ? mie : 0.f;
        o.z = (j0 + 2 == month) ? mie : 0.f;
        o.w = (j0 + 3 == month) ? mie : 0.f;
        stg_cs(ob + lane + 64, o);
    }
}

extern "C" void kernel_launch(void* const* d_in, const int* in_sizes, int n_in,
                              void* d_out, int out_size)
{
    const float* topic_emb = (const float*)d_in[0];
    const int*   noun_ids  = (const int*)  d_in[1];
    const int*   lengths   = (const int*)  d_in[2];
    const int*   months    = (const int*)  d_in[3];
    const void*  mie       = (const void*) d_in[4];
    const float* we        = (const float*)d_in[5];
    const float* k_w       = (const float*)d_in[6];
    const float* q_w       = (const float*)d_in[8];
    const float* q_b       = (const float*)d_in[9];
    float* out = (float*)d_out;

    const int B = in_sizes[2];

    prep_kernel<<<1, 320>>>(topic_emb, k_w, q_w, q_b);
    attn_kernel<<<(B + 3) / 4, 128>>>(noun_ids, lengths, months, mie, we, out, B);
}

// round 7
// speedup vs baseline: 1.6259x; 1.6259x over previous
#include <cuda_runtime.h>

// TopicNounAttention — warp-per-sample, un-normalized softmax (scores O(1) by
// construction; k_w ~1/sqrt(312), q_w ~1/sqrt(128) -> |s| <~ 6, fp32 exp safe).
// R7 = R3 structure (best: 37.4us) with:
//   - 32-thread blocks (1 warp = 1 sample = 1 CTA): uniform-random lengths 0..32
//     made 4-warp CTAs hold their slot until the slowest warp (E[max4]=29 vs
//     E[len]=16) -> CTA-granularity retirement fixes achieved-occupancy.
//   - next-token id shfl hoisted one iteration ahead (SHFL lat 26 was gating
//     every row's load-issue).
//   - all R5/R6 cache-policy hints reverted (measured regression).

#define VOCAB   50000
#define D_WORD  300
#define D_TOPIC 128
#define DH      312
#define LMAX    32

__device__ __align__(16) float g_ws[320];  // scaled projection vector, zero-padded

__global__ void prep_kernel(const float* __restrict__ topic_emb,
                            const float* __restrict__ k_w,
                            const float* __restrict__ q_w,
                            const float* __restrict__ q_b)
{
    __shared__ float te[D_TOPIC];
    __shared__ float q[D_TOPIC];
    const int t = threadIdx.x;
    if (t < D_TOPIC) te[t] = topic_emb[t];
    __syncthreads();
    if (t < D_TOPIC) {
        const float* row = q_w + t * D_TOPIC;
        float p0 = 0.f, p1 = 0.f, p2 = 0.f, p3 = 0.f;
        #pragma unroll
        for (int j = 0; j < D_TOPIC; j += 4) {
            p0 += row[j]     * te[j];
            p1 += row[j + 1] * te[j + 1];
            p2 += row[j + 2] * te[j + 2];
            p3 += row[j + 3] * te[j + 3];
        }
        q[t] = q_b[t] + (p0 + p1) + (p2 + p3);
    }
    __syncthreads();
    const float scale = 0.0883883476483184406f;  // 1/sqrt(128)
    if (t < 320) {
        float acc = 0.f;
        if (t < DH) {
            float p0 = 0.f, p1 = 0.f, p2 = 0.f, p3 = 0.f;
            #pragma unroll
            for (int i = 0; i < D_TOPIC; i += 4) {
                p0 += k_w[(i)     * DH + t] * q[i];
                p1 += k_w[(i + 1) * DH + t] * q[i + 1];
                p2 += k_w[(i + 2) * DH + t] * q[i + 2];
                p3 += k_w[(i + 3) * DH + t] * q[i + 3];
            }
            acc = ((p0 + p1) + (p2 + p3)) * scale;
        }
        g_ws[t] = acc;  // pads [312,320) with zero
    }
}

__device__ __forceinline__ float dot4(float4 a, float4 b) {
    return a.x * b.x + a.y * b.y + a.z * b.z + a.w * b.w;
}

__global__ void __launch_bounds__(32) attn_kernel(
    const int*   __restrict__ noun_ids,   // [B, 32]
    const int*   __restrict__ lengths,    // [B]
    const int*   __restrict__ months,     // [B]
    const void*  __restrict__ mie_ptr,    // scalar month_info_encode
    const float* __restrict__ we,         // [VOCAB, 300]
    float*       __restrict__ out)        // [B, 312]
{
    const int lane = threadIdx.x;
    const int b = blockIdx.x;

    float4* ob = reinterpret_cast<float4*>(out + (long long)b * DH);  // 1248B rows
    const int len0 = lengths[b];

    if (len0 <= 0) {
        const float4 z = make_float4(0.f, 0.f, 0.f, 0.f);
        ob[lane] = z; ob[lane + 32] = z;
        if (lane < 14) ob[lane + 64] = z;
        return;
    }
    const int len   = (len0 < LMAX) ? len0 : LMAX;
    const int month = months[b];
    const unsigned mu = *(const unsigned*)mie_ptr;
    const float mie = (mu < 0x10000u) ? (float)(int)mu : __uint_as_float(mu);

    // projection vector slice in registers (w2 zero-padded for lanes >= 11)
    const float4* wsv = reinterpret_cast<const float4*>(g_ws);
    const float4 w0 = wsv[lane];
    const float4 w1 = wsv[lane + 32];
    float4 w2 = make_float4(0.f, 0.f, 0.f, 0.f);
    const bool tail = (lane < 11);
    if (tail) w2 = wsv[lane + 64];

    const int ids = noun_ids[b * LMAX + lane];

    float4 a0 = make_float4(0.f, 0.f, 0.f, 0.f), a1 = a0, a2 = a0;
    float denom = 0.f;

    // row pointer for token 0; next token's id shfl hoisted one iter ahead so
    // the 26-cyc SHFL isn't on the load-issue critical path
    const float4* r = reinterpret_cast<const float4*>(
        we + (long long)__shfl_sync(0xffffffffu, ids, 0) * D_WORD);

    #pragma unroll 2
    for (int l = 0; l < len; ++l) {
        const float4* rcur = r;
        const int idn = __shfl_sync(0xffffffffu, ids, (l + 1) & 31);
        r = reinterpret_cast<const float4*>(we + (long long)idn * D_WORD);

        const float4 e0 = rcur[lane];
        const float4 e1 = rcur[lane + 32];
        float4 e2 = make_float4(0.f, 0.f, 0.f, 0.f);
        if (tail) e2 = rcur[lane + 64];   // predicated: avoids OOB on last row

        float s = dot4(e0, w0) + dot4(e1, w1) + dot4(e2, w2);
        #pragma unroll
        for (int o = 16; o > 0; o >>= 1) s += __shfl_xor_sync(0xffffffffu, s, o);

        const float p = __expf(s);     // scores O(1): no max subtraction needed
        denom += p;
        a0.x += p * e0.x;  a0.y += p * e0.y;  a0.z += p * e0.z;  a0.w += p * e0.w;
        a1.x += p * e1.x;  a1.y += p * e1.y;  a1.z += p * e1.z;  a1.w += p * e1.w;
        a2.x += p * e2.x;  a2.y += p * e2.y;  a2.z += p * e2.z;  a2.w += p * e2.w;
    }

    const float inv = 1.f / denom;
    float4 o;
    o.x = a0.x * inv; o.y = a0.y * inv; o.z = a0.z * inv; o.w = a0.w * inv;
    ob[lane] = o;
    o.x = a1.x * inv; o.y = a1.y * inv; o.z = a1.z * inv; o.w = a1.w * inv;
    ob[lane + 32] = o;
    if (tail) {
        o.x = a2.x * inv; o.y = a2.y * inv; o.z = a2.z * inv; o.w = a2.w * inv;
        ob[lane + 64] = o;
    } else if (lane < 14) {
        const int j0 = 4 * lane + 256 - 300;   // month one-hot block d in [300,312)
        o.x = (j0 + 0 == month) ? mie : 0.f;
        o.y = (j0 + 1 == month) ? mie : 0.f;
        o.z = (j0 + 2 == month) ? mie : 0.f;
        o.w = (j0 + 3 == month) ? mie : 0.f;
        ob[lane + 64] = o;
    }
}

extern "C" void kernel_launch(void* const* d_in, const int* in_sizes, int n_in,
                              void* d_out, int out_size)
{
    const float* topic_emb = (const float*)d_in[0];
    const int*   noun_ids  = (const int*)  d_in[1];
    const int*   lengths   = (const int*)  d_in[2];
    const int*   months    = (const int*)  d_in[3];
    const void*  mie       = (const void*) d_in[4];
    const float* we        = (const float*)d_in[5];
    const float* k_w       = (const float*)d_in[6];
    const float* q_w       = (const float*)d_in[8];
    const float* q_b       = (const float*)d_in[9];
    float* out = (float*)d_out;

    const int B = in_sizes[2];

    prep_kernel<<<1, 320>>>(topic_emb, k_w, q_w, q_b);
    attn_kernel<<<B, 32>>>(noun_ids, lengths, months, mie, we, out);
}